// round 3
// baseline (speedup 1.0000x reference)
#include <cuda_runtime.h>
#include <stdint.h>

#define NN   50000
#define EE   800000
#define DD   128
#define CC   32
#define TOT  6400000   // NN*DD

// ---------------- scratch (static device globals; no runtime alloc) ----------------
__device__ int   g_cnt[NN];
__device__ int   g_cursor[NN];
__device__ int   g_off[NN + 1];
__device__ float g_dinv[NN];
__device__ int   g_csr[EE];
__device__ float g_h1[NN * DD];   // x @ W1
__device__ float g_a1[NN * DD];   // aggregated + relu (+ dropout in place)
__device__ float g_h2[NN * CC];   // a1 @ W2

// ---------------- graph prep ----------------
__global__ void k_zero() {
    int i = blockIdx.x * blockDim.x + threadIdx.x;
    if (i < NN) { g_cnt[i] = 0; g_cursor[i] = 0; }
}

__global__ void k_hist(const int* __restrict__ ei) {
    int e = blockIdx.x * blockDim.x + threadIdx.x;
    if (e < EE) atomicAdd(&g_cnt[ei[EE + e]], 1);
}

// single-block shfl scan over NN counts -> exclusive offsets; also dinv = rsqrt(cnt+1)
__global__ void k_scan() {
    __shared__ int wsum[32];
    __shared__ int s_carry;
    int tid = threadIdx.x, lane = tid & 31, wid = tid >> 5;
    if (tid == 0) s_carry = 0;
    __syncthreads();
    for (int base = 0; base < NN; base += 1024) {
        int idx = base + tid;
        int v = (idx < NN) ? g_cnt[idx] : 0;
        if (idx < NN) g_dinv[idx] = rsqrtf((float)(v + 1));
        int x = v;
        #pragma unroll
        for (int o = 1; o < 32; o <<= 1) {
            int t = __shfl_up_sync(0xffffffffu, x, o);
            if (lane >= o) x += t;
        }
        if (lane == 31) wsum[wid] = x;
        __syncthreads();
        if (wid == 0) {
            int y = wsum[lane];
            #pragma unroll
            for (int o = 1; o < 32; o <<= 1) {
                int t = __shfl_up_sync(0xffffffffu, y, o);
                if (lane >= o) y += t;
            }
            wsum[lane] = y;
        }
        __syncthreads();
        int carry = s_carry;
        int incl = x + (wid > 0 ? wsum[wid - 1] : 0);
        if (idx < NN) g_off[idx] = carry + incl - v;
        __syncthreads();
        if (tid == 1023) s_carry = carry + incl;
        __syncthreads();
    }
    if (threadIdx.x == 0) g_off[NN] = s_carry;
}

__global__ void k_scatter(const int* __restrict__ ei) {
    int e = blockIdx.x * blockDim.x + threadIdx.x;
    if (e < EE) {
        int s = ei[e];
        int d = ei[EE + e];
        int pos = g_off[d] + atomicAdd(&g_cursor[d], 1);
        g_csr[pos] = s;
    }
}

// ---------------- GEMM1: h1[50000,128] = X[50000,128] @ W1[128,128] ----------------
// BM=64, BN=128, BK=32, 256 threads, 8x4 micro-tile
__global__ void k_gemm1(const float* __restrict__ X, const float* __restrict__ W) {
    __shared__ float As[32][72];    // [k][m], pad to 72 (288B rows, float4-aligned)
    __shared__ float Bs[32][128];
    int m0 = blockIdx.x * 64;
    int tid = threadIdx.x;
    int tx = tid & 31;   // col group: cols tx*4 .. tx*4+3
    int ty = tid >> 5;   // row group: rows ty*8 .. ty*8+7
    float acc[8][4];
    #pragma unroll
    for (int i = 0; i < 8; i++)
        #pragma unroll
        for (int j = 0; j < 4; j++) acc[i][j] = 0.f;

    for (int kc = 0; kc < 128; kc += 32) {
        // A tile: 64 rows x 8 float4 (transpose into As[k][m])
        #pragma unroll
        for (int t = tid; t < 512; t += 256) {
            int m = t >> 3, q = t & 7;
            int gm = m0 + m;
            float4 v = make_float4(0.f, 0.f, 0.f, 0.f);
            if (gm < NN) v = *(const float4*)(X + (size_t)gm * 128 + kc + q * 4);
            As[q * 4 + 0][m] = v.x;
            As[q * 4 + 1][m] = v.y;
            As[q * 4 + 2][m] = v.z;
            As[q * 4 + 3][m] = v.w;
        }
        // B tile: 32 rows x 32 float4
        #pragma unroll
        for (int t = tid; t < 1024; t += 256) {
            int k = t >> 5, q = t & 31;
            *(float4*)&Bs[k][q * 4] = *(const float4*)(W + (size_t)(kc + k) * 128 + q * 4);
        }
        __syncthreads();
        #pragma unroll
        for (int k = 0; k < 32; k++) {
            float4 a0 = *(const float4*)&As[k][ty * 8];
            float4 a1 = *(const float4*)&As[k][ty * 8 + 4];
            float4 b  = *(const float4*)&Bs[k][tx * 4];
            float av[8] = {a0.x, a0.y, a0.z, a0.w, a1.x, a1.y, a1.z, a1.w};
            float bv[4] = {b.x, b.y, b.z, b.w};
            #pragma unroll
            for (int i = 0; i < 8; i++)
                #pragma unroll
                for (int j = 0; j < 4; j++) acc[i][j] += av[i] * bv[j];
        }
        __syncthreads();
    }
    #pragma unroll
    for (int i = 0; i < 8; i++) {
        int gm = m0 + ty * 8 + i;
        if (gm < NN) {
            float4 o = make_float4(acc[i][0], acc[i][1], acc[i][2], acc[i][3]);
            *(float4*)(g_h1 + (size_t)gm * 128 + tx * 4) = o;
        }
    }
}

// ---------------- aggregate layer 1 (+ bias + relu) ----------------
// one block (128 threads) per node; thread f handles feature f
__global__ void k_agg1(const float* __restrict__ b1) {
    int v = blockIdx.x;
    int f = threadIdx.x;
    __shared__ int   sidx[128];
    __shared__ float sw[128];
    int beg = g_off[v], end = g_off[v + 1];
    float dv = g_dinv[v];
    float acc = g_h1[(size_t)v * 128 + f] * dv;   // self-loop term (×dv again below -> dv^2)
    for (int base = beg; base < end; base += 128) {
        int n = min(128, end - base);
        if (f < n) {
            int s = g_csr[base + f];
            sidx[f] = s;
            sw[f] = g_dinv[s];
        }
        __syncthreads();
        #pragma unroll 4
        for (int j = 0; j < n; j++)
            acc += g_h1[(size_t)sidx[j] * 128 + f] * sw[j];
        __syncthreads();
    }
    float r = acc * dv + b1[f];
    g_a1[(size_t)v * 128 + f] = fmaxf(r, 0.f);
}

// ---------------- dropout: JAX partitionable threefry2x32, key (0, 42) ----------------
// Per-element i: counter64 = flat index -> words (hi, lo) = (0, i) for i < 2^32.
// For bit_width < 64, partitionable random_bits returns (x0 ^ x1) truncated,
// i.e. 32-bit bits = x0_out ^ x1_out.
// uniform<0.5  <=>  MSB(bits)==0 ; keep -> *2
__device__ __forceinline__ void threefry(uint32_t c0, uint32_t c1,
                                         uint32_t& o0, uint32_t& o1) {
    const uint32_t ks0 = 0u;
    const uint32_t ks1 = 42u;
    const uint32_t ks2 = 0x1BD11BDAu ^ 0u ^ 42u;
    uint32_t x0 = c0 + ks0;
    uint32_t x1 = c1 + ks1;
#define TF_R(r) { x0 += x1; x1 = __funnelshift_l(x1, x1, (r)); x1 ^= x0; }
    TF_R(13) TF_R(15) TF_R(26) TF_R(6)
    x0 += ks1; x1 += ks2 + 1u;
    TF_R(17) TF_R(29) TF_R(16) TF_R(24)
    x0 += ks2; x1 += ks0 + 2u;
    TF_R(13) TF_R(15) TF_R(26) TF_R(6)
    x0 += ks0; x1 += ks1 + 3u;
    TF_R(17) TF_R(29) TF_R(16) TF_R(24)
    x0 += ks1; x1 += ks2 + 4u;
    TF_R(13) TF_R(15) TF_R(26) TF_R(6)
    x0 += ks2; x1 += ks0 + 5u;
#undef TF_R
    o0 = x0; o1 = x1;
}

__global__ void k_drop() {
    int i = blockIdx.x * blockDim.x + threadIdx.x;
    if (i >= TOT) return;
    uint32_t x0, x1;
    threefry(0u, (uint32_t)i, x0, x1);
    uint32_t bits = x0 ^ x1;
    float v = g_a1[i];
    g_a1[i] = (bits & 0x80000000u) ? 0.f : v * 2.f;
}

// ---------------- GEMM2: h2[50000,32] = a1[50000,128] @ W2[128,32] ----------------
// BM=128, BN=32, BK=32, 256 threads, 4x4 micro-tile
__global__ void k_gemm2(const float* __restrict__ W) {
    __shared__ float As[32][132];   // [k][m], pad 132 (528B rows, float4-aligned)
    __shared__ float Bs[32][32];
    int m0 = blockIdx.x * 128;
    int tid = threadIdx.x;
    int tx = tid & 7;    // cols tx*4 .. +3
    int ty = tid >> 3;   // rows ty*4 .. +3
    float acc[4][4];
    #pragma unroll
    for (int i = 0; i < 4; i++)
        #pragma unroll
        for (int j = 0; j < 4; j++) acc[i][j] = 0.f;

    for (int kc = 0; kc < 128; kc += 32) {
        #pragma unroll
        for (int t = tid; t < 1024; t += 256) {
            int m = t >> 3, q = t & 7;
            int gm = m0 + m;
            float4 v = make_float4(0.f, 0.f, 0.f, 0.f);
            if (gm < NN) v = *(const float4*)(g_a1 + (size_t)gm * 128 + kc + q * 4);
            As[q * 4 + 0][m] = v.x;
            As[q * 4 + 1][m] = v.y;
            As[q * 4 + 2][m] = v.z;
            As[q * 4 + 3][m] = v.w;
        }
        {
            int t = tid;
            if (t < 256) {
                int k = t >> 3, q = t & 7;
                *(float4*)&Bs[k][q * 4] = *(const float4*)(W + (size_t)(kc + k) * 32 + q * 4);
            }
        }
        __syncthreads();
        #pragma unroll
        for (int k = 0; k < 32; k++) {
            float4 a = *(const float4*)&As[k][ty * 4];
            float4 b = *(const float4*)&Bs[k][tx * 4];
            float av[4] = {a.x, a.y, a.z, a.w};
            float bv[4] = {b.x, b.y, b.z, b.w};
            #pragma unroll
            for (int i = 0; i < 4; i++)
                #pragma unroll
                for (int j = 0; j < 4; j++) acc[i][j] += av[i] * bv[j];
        }
        __syncthreads();
    }
    #pragma unroll
    for (int i = 0; i < 4; i++) {
        int gm = m0 + ty * 4 + i;
        if (gm < NN) {
            float4 o = make_float4(acc[i][0], acc[i][1], acc[i][2], acc[i][3]);
            *(float4*)(g_h2 + (size_t)gm * 32 + tx * 4) = o;
        }
    }
}

// ---------------- aggregate layer 2 + bias + log_softmax ----------------
// blockDim (32,4): warp per node, lane per class
__global__ void k_agg2(const float* __restrict__ b2, float* __restrict__ out) {
    int v = blockIdx.x * 4 + threadIdx.y;
    if (v >= NN) return;
    int lane = threadIdx.x;
    int beg = g_off[v], end = g_off[v + 1];
    float dv = g_dinv[v];
    float acc = g_h2[(size_t)v * 32 + lane] * dv;
    for (int e = beg; e < end; e++) {
        int s = g_csr[e];                    // broadcast load
        acc += g_h2[(size_t)s * 32 + lane] * g_dinv[s];
    }
    acc = acc * dv + b2[lane];
    // log_softmax over 32 lanes
    float m = acc;
    #pragma unroll
    for (int o = 16; o > 0; o >>= 1) m = fmaxf(m, __shfl_xor_sync(0xffffffffu, m, o));
    float ex = expf(acc - m);
    float s = ex;
    #pragma unroll
    for (int o = 16; o > 0; o >>= 1) s += __shfl_xor_sync(0xffffffffu, s, o);
    out[(size_t)v * 32 + lane] = acc - m - logf(s);
}

// ---------------- launcher ----------------
extern "C" void kernel_launch(void* const* d_in, const int* in_sizes, int n_in,
                              void* d_out, int out_size) {
    const float* x  = (const float*)d_in[0];
    const float* W1 = (const float*)d_in[1];
    const float* b1 = (const float*)d_in[2];
    const float* W2 = (const float*)d_in[3];
    const float* b2 = (const float*)d_in[4];
    const int*   ei = (const int*)d_in[5];
    float* out = (float*)d_out;

    k_zero   <<<(NN + 255) / 256, 256>>>();
    k_hist   <<<(EE + 255) / 256, 256>>>(ei);
    k_scan   <<<1, 1024>>>();
    k_scatter<<<(EE + 255) / 256, 256>>>(ei);
    k_gemm1  <<<(NN + 63) / 64, 256>>>(x, W1);
    k_agg1   <<<NN, 128>>>(b1);
    k_drop   <<<(TOT + 255) / 256, 256>>>();
    k_gemm2  <<<(NN + 127) / 128, 256>>>(W2);
    k_agg2   <<<(NN + 3) / 4, dim3(32, 4)>>>(b2, out);
}

// round 4
// speedup vs baseline: 1.1195x; 1.1195x over previous
#include <cuda_runtime.h>
#include <stdint.h>

#define NN   50000
#define EE   800000
#define DD   128
#define CC   32

// ---------------- scratch (static device globals; no runtime alloc) ----------------
__device__ int   g_cnt[NN];
__device__ int   g_cursor[NN];
__device__ int   g_off[NN + 1];
__device__ float g_dinv[NN];
__device__ int   g_csr[EE];
__device__ float g_h1[NN * DD];   // x @ W1
__device__ float g_a1[NN * DD];   // aggregated + relu + dropout
__device__ float g_h2[NN * CC];   // a1 @ W2

// ---------------- graph prep ----------------
__global__ void k_zero() {
    int i = blockIdx.x * blockDim.x + threadIdx.x;
    if (i < NN) g_cnt[i] = 0;
}

// 4 edges per thread, int4 loads -> 4 outstanding atomics per thread
__global__ void k_hist(const int* __restrict__ ei) {
    int t = blockIdx.x * blockDim.x + threadIdx.x;
    int e = t * 4;
    if (e < EE) {
        int4 d = *(const int4*)(ei + EE + e);
        atomicAdd(&g_cnt[d.x], 1);
        atomicAdd(&g_cnt[d.y], 1);
        atomicAdd(&g_cnt[d.z], 1);
        atomicAdd(&g_cnt[d.w], 1);
    }
}

// single-block shfl scan over NN counts -> exclusive offsets; dinv = rsqrt(cnt+1);
// cursor pre-seeded with offsets (saves a dependent load in k_scatter)
__global__ void k_scan() {
    __shared__ int wsum[32];
    __shared__ int s_carry;
    int tid = threadIdx.x, lane = tid & 31, wid = tid >> 5;
    if (tid == 0) s_carry = 0;
    __syncthreads();
    for (int base = 0; base < NN; base += 1024) {
        int idx = base + tid;
        int v = (idx < NN) ? g_cnt[idx] : 0;
        if (idx < NN) g_dinv[idx] = rsqrtf((float)(v + 1));
        int x = v;
        #pragma unroll
        for (int o = 1; o < 32; o <<= 1) {
            int t2 = __shfl_up_sync(0xffffffffu, x, o);
            if (lane >= o) x += t2;
        }
        if (lane == 31) wsum[wid] = x;
        __syncthreads();
        if (wid == 0) {
            int y = wsum[lane];
            #pragma unroll
            for (int o = 1; o < 32; o <<= 1) {
                int t2 = __shfl_up_sync(0xffffffffu, y, o);
                if (lane >= o) y += t2;
            }
            wsum[lane] = y;
        }
        __syncthreads();
        int carry = s_carry;
        int incl = x + (wid > 0 ? wsum[wid - 1] : 0);
        if (idx < NN) {
            int off = carry + incl - v;
            g_off[idx] = off;
            g_cursor[idx] = off;
        }
        __syncthreads();
        if (tid == 1023) s_carry = carry + incl;
        __syncthreads();
    }
    if (threadIdx.x == 0) g_off[NN] = s_carry;
}

// 4 edges per thread, cursor already holds base offsets
__global__ void k_scatter(const int* __restrict__ ei) {
    int t = blockIdx.x * blockDim.x + threadIdx.x;
    int e = t * 4;
    if (e < EE) {
        int4 s = *(const int4*)(ei + e);
        int4 d = *(const int4*)(ei + EE + e);
        g_csr[atomicAdd(&g_cursor[d.x], 1)] = s.x;
        g_csr[atomicAdd(&g_cursor[d.y], 1)] = s.y;
        g_csr[atomicAdd(&g_cursor[d.z], 1)] = s.z;
        g_csr[atomicAdd(&g_cursor[d.w], 1)] = s.w;
    }
}

// ---------------- GEMM1: h1[50000,128] = X[50000,128] @ W1[128,128] ----------------
__global__ void k_gemm1(const float* __restrict__ X, const float* __restrict__ W) {
    __shared__ float As[32][72];
    __shared__ float Bs[32][128];
    int m0 = blockIdx.x * 64;
    int tid = threadIdx.x;
    int tx = tid & 31;
    int ty = tid >> 5;
    float acc[8][4];
    #pragma unroll
    for (int i = 0; i < 8; i++)
        #pragma unroll
        for (int j = 0; j < 4; j++) acc[i][j] = 0.f;

    for (int kc = 0; kc < 128; kc += 32) {
        #pragma unroll
        for (int t = tid; t < 512; t += 256) {
            int m = t >> 3, q = t & 7;
            int gm = m0 + m;
            float4 v = make_float4(0.f, 0.f, 0.f, 0.f);
            if (gm < NN) v = *(const float4*)(X + (size_t)gm * 128 + kc + q * 4);
            As[q * 4 + 0][m] = v.x;
            As[q * 4 + 1][m] = v.y;
            As[q * 4 + 2][m] = v.z;
            As[q * 4 + 3][m] = v.w;
        }
        #pragma unroll
        for (int t = tid; t < 1024; t += 256) {
            int k = t >> 5, q = t & 31;
            *(float4*)&Bs[k][q * 4] = *(const float4*)(W + (size_t)(kc + k) * 128 + q * 4);
        }
        __syncthreads();
        #pragma unroll
        for (int k = 0; k < 32; k++) {
            float4 a0 = *(const float4*)&As[k][ty * 8];
            float4 a1 = *(const float4*)&As[k][ty * 8 + 4];
            float4 b  = *(const float4*)&Bs[k][tx * 4];
            float av[8] = {a0.x, a0.y, a0.z, a0.w, a1.x, a1.y, a1.z, a1.w};
            float bv[4] = {b.x, b.y, b.z, b.w};
            #pragma unroll
            for (int i = 0; i < 8; i++)
                #pragma unroll
                for (int j = 0; j < 4; j++) acc[i][j] += av[i] * bv[j];
        }
        __syncthreads();
    }
    #pragma unroll
    for (int i = 0; i < 8; i++) {
        int gm = m0 + ty * 8 + i;
        if (gm < NN) {
            float4 o = make_float4(acc[i][0], acc[i][1], acc[i][2], acc[i][3]);
            *(float4*)(g_h1 + (size_t)gm * 128 + tx * 4) = o;
        }
    }
}

// ---------------- threefry (JAX partitionable, key (0,42)) ----------------
__device__ __forceinline__ uint32_t tf_bits(uint32_t c1) {
    const uint32_t ks0 = 0u;
    const uint32_t ks1 = 42u;
    const uint32_t ks2 = 0x1BD11BDAu ^ 0u ^ 42u;
    uint32_t x0 = 0u + ks0;      // counter hi word = 0
    uint32_t x1 = c1 + ks1;
#define TF_R(r) { x0 += x1; x1 = __funnelshift_l(x1, x1, (r)); x1 ^= x0; }
    TF_R(13) TF_R(15) TF_R(26) TF_R(6)
    x0 += ks1; x1 += ks2 + 1u;
    TF_R(17) TF_R(29) TF_R(16) TF_R(24)
    x0 += ks2; x1 += ks0 + 2u;
    TF_R(13) TF_R(15) TF_R(26) TF_R(6)
    x0 += ks0; x1 += ks1 + 3u;
    TF_R(17) TF_R(29) TF_R(16) TF_R(24)
    x0 += ks1; x1 += ks2 + 4u;
    TF_R(13) TF_R(15) TF_R(26) TF_R(6)
    x0 += ks2; x1 += ks0 + 5u;
#undef TF_R
    return x0 ^ x1;   // 32-bit random_bits = XOR fold of the two output words
}

// ---------------- aggregate layer 1 + bias + relu + dropout (fused) -----------
// warp per node, lane handles features [4*lane, 4*lane+4) via float4
__global__ void k_agg1(const float* __restrict__ b1) {
    int w = (blockIdx.x * blockDim.x + threadIdx.x) >> 5;
    int lane = threadIdx.x & 31;
    if (w >= NN) return;
    int v = w;
    int beg = g_off[v], end = g_off[v + 1];
    float dv = g_dinv[v];

    float4 a = *(const float4*)(g_h1 + (size_t)v * 128 + lane * 4);
    float4 acc = make_float4(a.x * dv, a.y * dv, a.z * dv, a.w * dv);  // self-loop

    for (int base = beg; base < end; base += 32) {
        int n = end - base;
        int idx = 0; float wt = 0.f;
        if (lane < n) { idx = g_csr[base + lane]; wt = g_dinv[idx]; }
        int m = n < 32 ? n : 32;
        for (int j = 0; j < m; j++) {
            int   s  = __shfl_sync(0xffffffffu, idx, j);
            float wj = __shfl_sync(0xffffffffu, wt, j);
            float4 hv = *(const float4*)(g_h1 + (size_t)s * 128 + lane * 4);
            acc.x += hv.x * wj;
            acc.y += hv.y * wj;
            acc.z += hv.z * wj;
            acc.w += hv.w * wj;
        }
    }
    float4 bb = *(const float4*)(b1 + lane * 4);
    float r[4];
    r[0] = fmaxf(acc.x * dv + bb.x, 0.f);
    r[1] = fmaxf(acc.y * dv + bb.y, 0.f);
    r[2] = fmaxf(acc.z * dv + bb.z, 0.f);
    r[3] = fmaxf(acc.w * dv + bb.w, 0.f);

    uint32_t i0 = (uint32_t)v * 128u + (uint32_t)lane * 4u;
    #pragma unroll
    for (int q = 0; q < 4; q++) {
        uint32_t bits = tf_bits(i0 + q);
        r[q] = (bits & 0x80000000u) ? 0.f : r[q] * 2.f;
    }
    *(float4*)(g_a1 + (size_t)v * 128 + lane * 4) = make_float4(r[0], r[1], r[2], r[3]);
}

// ---------------- GEMM2: h2[50000,32] = a1[50000,128] @ W2[128,32] ----------------
__global__ void k_gemm2(const float* __restrict__ W) {
    __shared__ float As[32][132];
    __shared__ float Bs[32][32];
    int m0 = blockIdx.x * 128;
    int tid = threadIdx.x;
    int tx = tid & 7;
    int ty = tid >> 3;
    float acc[4][4];
    #pragma unroll
    for (int i = 0; i < 4; i++)
        #pragma unroll
        for (int j = 0; j < 4; j++) acc[i][j] = 0.f;

    for (int kc = 0; kc < 128; kc += 32) {
        #pragma unroll
        for (int t = tid; t < 1024; t += 256) {
            int m = t >> 3, q = t & 7;
            int gm = m0 + m;
            float4 v = make_float4(0.f, 0.f, 0.f, 0.f);
            if (gm < NN) v = *(const float4*)(g_a1 + (size_t)gm * 128 + kc + q * 4);
            As[q * 4 + 0][m] = v.x;
            As[q * 4 + 1][m] = v.y;
            As[q * 4 + 2][m] = v.z;
            As[q * 4 + 3][m] = v.w;
        }
        if (tid < 256) {
            int k = tid >> 3, q = tid & 7;
            *(float4*)&Bs[k][q * 4] = *(const float4*)(W + (size_t)(kc + k) * 32 + q * 4);
        }
        __syncthreads();
        #pragma unroll
        for (int k = 0; k < 32; k++) {
            float4 a = *(const float4*)&As[k][ty * 4];
            float4 b = *(const float4*)&Bs[k][tx * 4];
            float av[4] = {a.x, a.y, a.z, a.w};
            float bv[4] = {b.x, b.y, b.z, b.w};
            #pragma unroll
            for (int i = 0; i < 4; i++)
                #pragma unroll
                for (int j = 0; j < 4; j++) acc[i][j] += av[i] * bv[j];
        }
        __syncthreads();
    }
    #pragma unroll
    for (int i = 0; i < 4; i++) {
        int gm = m0 + ty * 4 + i;
        if (gm < NN) {
            float4 o = make_float4(acc[i][0], acc[i][1], acc[i][2], acc[i][3]);
            *(float4*)(g_h2 + (size_t)gm * 32 + tx * 4) = o;
        }
    }
}

// ---------------- aggregate layer 2 + bias + log_softmax ----------------
// warp per node, lane per class, shfl-batched neighbors
__global__ void k_agg2(const float* __restrict__ b2, float* __restrict__ out) {
    int w = (blockIdx.x * blockDim.x + threadIdx.x) >> 5;
    int lane = threadIdx.x & 31;
    if (w >= NN) return;
    int v = w;
    int beg = g_off[v], end = g_off[v + 1];
    float dv = g_dinv[v];
    float acc = g_h2[(size_t)v * 32 + lane] * dv;

    for (int base = beg; base < end; base += 32) {
        int n = end - base;
        int idx = 0; float wt = 0.f;
        if (lane < n) { idx = g_csr[base + lane]; wt = g_dinv[idx]; }
        int m = n < 32 ? n : 32;
        for (int j = 0; j < m; j++) {
            int   s  = __shfl_sync(0xffffffffu, idx, j);
            float wj = __shfl_sync(0xffffffffu, wt, j);
            acc += g_h2[(size_t)s * 32 + lane] * wj;
        }
    }
    acc = acc * dv + b2[lane];
    // log_softmax over 32 lanes
    float mx = acc;
    #pragma unroll
    for (int o = 16; o > 0; o >>= 1) mx = fmaxf(mx, __shfl_xor_sync(0xffffffffu, mx, o));
    float ex = expf(acc - mx);
    float s = ex;
    #pragma unroll
    for (int o = 16; o > 0; o >>= 1) s += __shfl_xor_sync(0xffffffffu, s, o);
    out[(size_t)v * 32 + lane] = acc - mx - logf(s);
}

// ---------------- launcher ----------------
extern "C" void kernel_launch(void* const* d_in, const int* in_sizes, int n_in,
                              void* d_out, int out_size) {
    const float* x  = (const float*)d_in[0];
    const float* W1 = (const float*)d_in[1];
    const float* b1 = (const float*)d_in[2];
    const float* W2 = (const float*)d_in[3];
    const float* b2 = (const float*)d_in[4];
    const int*   ei = (const int*)d_in[5];
    float* out = (float*)d_out;

    k_zero   <<<(NN + 255) / 256, 256>>>();
    k_hist   <<<(EE / 4 + 255) / 256, 256>>>(ei);
    k_scan   <<<1, 1024>>>();
    k_scatter<<<(EE / 4 + 255) / 256, 256>>>(ei);
    k_gemm1  <<<(NN + 63) / 64, 256>>>(x, W1);
    k_agg1   <<<(NN * 32 + 255) / 256, 256>>>(b1);
    k_gemm2  <<<(NN + 127) / 128, 256>>>(W2);
    k_agg2   <<<(NN * 32 + 255) / 256, 256>>>(b2, out);
}

// round 5
// speedup vs baseline: 1.4530x; 1.2979x over previous
#include <cuda_runtime.h>
#include <stdint.h>

#define NN   50000
#define EE   800000
#define DD   128
#define CC   32
#define SCAN_B 1024
#define NB   ((NN + SCAN_B - 1) / SCAN_B)   // 49 scan blocks

// ---------------- scratch (static device globals; no runtime alloc) ----------------
__device__ int   g_cnt[NN];
__device__ int   g_cursor[NN];
__device__ int   g_off[NN + 1];
__device__ float g_dinv[NN];
__device__ int   g_csr[EE];
__device__ int   g_bsum[NB];
__device__ int   g_bpre[NB];
__device__ float g_h1[NN * DD];   // x @ W1
__device__ float g_a1[NN * DD];   // aggregated + relu + dropout
__device__ float g_h2[NN * CC];   // a1 @ W2

// ---------------- graph prep ----------------
__global__ void k_zero() {
    int i = blockIdx.x * blockDim.x + threadIdx.x;
    if (i < NN) g_cnt[i] = 0;
}

// 4 edges per thread, int4 loads -> 4 outstanding atomics per thread
__global__ void k_hist(const int* __restrict__ ei) {
    int t = blockIdx.x * blockDim.x + threadIdx.x;
    int e = t * 4;
    if (e < EE) {
        int4 d = *(const int4*)(ei + EE + e);
        atomicAdd(&g_cnt[d.x], 1);
        atomicAdd(&g_cnt[d.y], 1);
        atomicAdd(&g_cnt[d.z], 1);
        atomicAdd(&g_cnt[d.w], 1);
    }
}

// ---- 3-kernel scan: block sums -> scan of 49 sums -> offsets + cursor ----
__global__ void k_bsum() {
    __shared__ int wsum[32];
    int idx = blockIdx.x * SCAN_B + threadIdx.x;
    int lane = threadIdx.x & 31, wid = threadIdx.x >> 5;
    int v = (idx < NN) ? g_cnt[idx] : 0;
    if (idx < NN) g_dinv[idx] = rsqrtf((float)(v + 1));
    int x = v;
    #pragma unroll
    for (int o = 16; o > 0; o >>= 1) x += __shfl_down_sync(0xffffffffu, x, o);
    if (lane == 0) wsum[wid] = x;
    __syncthreads();
    if (wid == 0) {
        int y = (lane < SCAN_B / 32) ? wsum[lane] : 0;
        #pragma unroll
        for (int o = 16; o > 0; o >>= 1) y += __shfl_down_sync(0xffffffffu, y, o);
        if (lane == 0) g_bsum[blockIdx.x] = y;
    }
}

__global__ void k_bscan() {
    // single warp scans NB<=49 block sums (two strips of 32)
    int lane = threadIdx.x;
    int carry = 0;
    for (int base = 0; base < NB; base += 32) {
        int i = base + lane;
        int v = (i < NB) ? g_bsum[i] : 0;
        int x = v;
        #pragma unroll
        for (int o = 1; o < 32; o <<= 1) {
            int t = __shfl_up_sync(0xffffffffu, x, o);
            if (lane >= o) x += t;
        }
        if (i < NB) g_bpre[i] = carry + x - v;   // exclusive
        carry += __shfl_sync(0xffffffffu, x, 31);
    }
    if (lane == 0) g_off[NN] = carry;
}

__global__ void k_off() {
    __shared__ int wsum[32];
    int idx = blockIdx.x * SCAN_B + threadIdx.x;
    int lane = threadIdx.x & 31, wid = threadIdx.x >> 5;
    int v = (idx < NN) ? g_cnt[idx] : 0;
    int x = v;
    #pragma unroll
    for (int o = 1; o < 32; o <<= 1) {
        int t = __shfl_up_sync(0xffffffffu, x, o);
        if (lane >= o) x += t;
    }
    if (lane == 31) wsum[wid] = x;
    __syncthreads();
    if (wid == 0) {
        int y = (lane < SCAN_B / 32) ? wsum[lane] : 0;
        #pragma unroll
        for (int o = 1; o < 32; o <<= 1) {
            int t = __shfl_up_sync(0xffffffffu, y, o);
            if (lane >= o) y += t;
        }
        wsum[lane] = y;
    }
    __syncthreads();
    if (idx < NN) {
        int off = g_bpre[blockIdx.x] + (wid > 0 ? wsum[wid - 1] : 0) + x - v;
        g_off[idx] = off;
        g_cursor[idx] = off;
    }
}

// 4 edges per thread, cursor pre-seeded with offsets
__global__ void k_scatter(const int* __restrict__ ei) {
    int t = blockIdx.x * blockDim.x + threadIdx.x;
    int e = t * 4;
    if (e < EE) {
        int4 s = *(const int4*)(ei + e);
        int4 d = *(const int4*)(ei + EE + e);
        g_csr[atomicAdd(&g_cursor[d.x], 1)] = s.x;
        g_csr[atomicAdd(&g_cursor[d.y], 1)] = s.y;
        g_csr[atomicAdd(&g_cursor[d.z], 1)] = s.z;
        g_csr[atomicAdd(&g_cursor[d.w], 1)] = s.w;
    }
}

// ---------------- GEMM1: h1[50000,128] = X[50000,128] @ W1[128,128] ----------------
__global__ void k_gemm1(const float* __restrict__ X, const float* __restrict__ W) {
    __shared__ float As[32][72];
    __shared__ float Bs[32][128];
    int m0 = blockIdx.x * 64;
    int tid = threadIdx.x;
    int tx = tid & 31;
    int ty = tid >> 5;
    float acc[8][4];
    #pragma unroll
    for (int i = 0; i < 8; i++)
        #pragma unroll
        for (int j = 0; j < 4; j++) acc[i][j] = 0.f;

    for (int kc = 0; kc < 128; kc += 32) {
        #pragma unroll
        for (int t = tid; t < 512; t += 256) {
            int m = t >> 3, q = t & 7;
            int gm = m0 + m;
            float4 v = make_float4(0.f, 0.f, 0.f, 0.f);
            if (gm < NN) v = *(const float4*)(X + (size_t)gm * 128 + kc + q * 4);
            As[q * 4 + 0][m] = v.x;
            As[q * 4 + 1][m] = v.y;
            As[q * 4 + 2][m] = v.z;
            As[q * 4 + 3][m] = v.w;
        }
        #pragma unroll
        for (int t = tid; t < 1024; t += 256) {
            int k = t >> 5, q = t & 31;
            *(float4*)&Bs[k][q * 4] = *(const float4*)(W + (size_t)(kc + k) * 128 + q * 4);
        }
        __syncthreads();
        #pragma unroll
        for (int k = 0; k < 32; k++) {
            float4 a0 = *(const float4*)&As[k][ty * 8];
            float4 a1 = *(const float4*)&As[k][ty * 8 + 4];
            float4 b  = *(const float4*)&Bs[k][tx * 4];
            float av[8] = {a0.x, a0.y, a0.z, a0.w, a1.x, a1.y, a1.z, a1.w};
            float bv[4] = {b.x, b.y, b.z, b.w};
            #pragma unroll
            for (int i = 0; i < 8; i++)
                #pragma unroll
                for (int j = 0; j < 4; j++) acc[i][j] += av[i] * bv[j];
        }
        __syncthreads();
    }
    #pragma unroll
    for (int i = 0; i < 8; i++) {
        int gm = m0 + ty * 8 + i;
        if (gm < NN) {
            float4 o = make_float4(acc[i][0], acc[i][1], acc[i][2], acc[i][3]);
            *(float4*)(g_h1 + (size_t)gm * 128 + tx * 4) = o;
        }
    }
}

// ---------------- threefry (JAX partitionable, key (0,42)) ----------------
__device__ __forceinline__ uint32_t tf_bits(uint32_t c1) {
    const uint32_t ks0 = 0u;
    const uint32_t ks1 = 42u;
    const uint32_t ks2 = 0x1BD11BDAu ^ 0u ^ 42u;
    uint32_t x0 = 0u + ks0;
    uint32_t x1 = c1 + ks1;
#define TF_R(r) { x0 += x1; x1 = __funnelshift_l(x1, x1, (r)); x1 ^= x0; }
    TF_R(13) TF_R(15) TF_R(26) TF_R(6)
    x0 += ks1; x1 += ks2 + 1u;
    TF_R(17) TF_R(29) TF_R(16) TF_R(24)
    x0 += ks2; x1 += ks0 + 2u;
    TF_R(13) TF_R(15) TF_R(26) TF_R(6)
    x0 += ks0; x1 += ks1 + 3u;
    TF_R(17) TF_R(29) TF_R(16) TF_R(24)
    x0 += ks1; x1 += ks2 + 4u;
    TF_R(13) TF_R(15) TF_R(26) TF_R(6)
    x0 += ks2; x1 += ks0 + 5u;
#undef TF_R
    return x0 ^ x1;
}

// ---------------- aggregate layer 1 + bias + relu + dropout (fused) -----------
__global__ void k_agg1(const float* __restrict__ b1) {
    int w = (blockIdx.x * blockDim.x + threadIdx.x) >> 5;
    int lane = threadIdx.x & 31;
    if (w >= NN) return;
    int v = w;
    int beg = g_off[v], end = g_off[v + 1];
    float dv = g_dinv[v];

    float4 a = *(const float4*)(g_h1 + (size_t)v * 128 + lane * 4);
    float4 acc = make_float4(a.x * dv, a.y * dv, a.z * dv, a.w * dv);

    for (int base = beg; base < end; base += 32) {
        int n = end - base;
        int idx = 0; float wt = 0.f;
        if (lane < n) { idx = g_csr[base + lane]; wt = g_dinv[idx]; }
        int m = n < 32 ? n : 32;
        for (int j = 0; j < m; j++) {
            int   s  = __shfl_sync(0xffffffffu, idx, j);
            float wj = __shfl_sync(0xffffffffu, wt, j);
            float4 hv = *(const float4*)(g_h1 + (size_t)s * 128 + lane * 4);
            acc.x += hv.x * wj;
            acc.y += hv.y * wj;
            acc.z += hv.z * wj;
            acc.w += hv.w * wj;
        }
    }
    float4 bb = *(const float4*)(b1 + lane * 4);
    float r[4];
    r[0] = fmaxf(acc.x * dv + bb.x, 0.f);
    r[1] = fmaxf(acc.y * dv + bb.y, 0.f);
    r[2] = fmaxf(acc.z * dv + bb.z, 0.f);
    r[3] = fmaxf(acc.w * dv + bb.w, 0.f);

    uint32_t i0 = (uint32_t)v * 128u + (uint32_t)lane * 4u;
    #pragma unroll
    for (int q = 0; q < 4; q++) {
        uint32_t bits = tf_bits(i0 + q);
        r[q] = (bits & 0x80000000u) ? 0.f : r[q] * 2.f;
    }
    *(float4*)(g_a1 + (size_t)v * 128 + lane * 4) = make_float4(r[0], r[1], r[2], r[3]);
}

// ---------------- GEMM2: h2[50000,32] = a1[50000,128] @ W2[128,32] ----------------
__global__ void k_gemm2(const float* __restrict__ W) {
    __shared__ float As[32][132];
    __shared__ float Bs[32][32];
    int m0 = blockIdx.x * 128;
    int tid = threadIdx.x;
    int tx = tid & 7;
    int ty = tid >> 3;
    float acc[4][4];
    #pragma unroll
    for (int i = 0; i < 4; i++)
        #pragma unroll
        for (int j = 0; j < 4; j++) acc[i][j] = 0.f;

    for (int kc = 0; kc < 128; kc += 32) {
        #pragma unroll
        for (int t = tid; t < 1024; t += 256) {
            int m = t >> 3, q = t & 7;
            int gm = m0 + m;
            float4 v = make_float4(0.f, 0.f, 0.f, 0.f);
            if (gm < NN) v = *(const float4*)(g_a1 + (size_t)gm * 128 + kc + q * 4);
            As[q * 4 + 0][m] = v.x;
            As[q * 4 + 1][m] = v.y;
            As[q * 4 + 2][m] = v.z;
            As[q * 4 + 3][m] = v.w;
        }
        if (tid < 256) {
            int k = tid >> 3, q = tid & 7;
            *(float4*)&Bs[k][q * 4] = *(const float4*)(W + (size_t)(kc + k) * 32 + q * 4);
        }
        __syncthreads();
        #pragma unroll
        for (int k = 0; k < 32; k++) {
            float4 a = *(const float4*)&As[k][ty * 4];
            float4 b = *(const float4*)&Bs[k][tx * 4];
            float av[4] = {a.x, a.y, a.z, a.w};
            float bv[4] = {b.x, b.y, b.z, b.w};
            #pragma unroll
            for (int i = 0; i < 4; i++)
                #pragma unroll
                for (int j = 0; j < 4; j++) acc[i][j] += av[i] * bv[j];
        }
        __syncthreads();
    }
    #pragma unroll
    for (int i = 0; i < 4; i++) {
        int gm = m0 + ty * 4 + i;
        if (gm < NN) {
            float4 o = make_float4(acc[i][0], acc[i][1], acc[i][2], acc[i][3]);
            *(float4*)(g_h2 + (size_t)gm * 32 + tx * 4) = o;
        }
    }
}

// ---------------- aggregate layer 2 + bias + log_softmax ----------------
__global__ void k_agg2(const float* __restrict__ b2, float* __restrict__ out) {
    int w = (blockIdx.x * blockDim.x + threadIdx.x) >> 5;
    int lane = threadIdx.x & 31;
    if (w >= NN) return;
    int v = w;
    int beg = g_off[v], end = g_off[v + 1];
    float dv = g_dinv[v];
    float acc = g_h2[(size_t)v * 32 + lane] * dv;

    for (int base = beg; base < end; base += 32) {
        int n = end - base;
        int idx = 0; float wt = 0.f;
        if (lane < n) { idx = g_csr[base + lane]; wt = g_dinv[idx]; }
        int m = n < 32 ? n : 32;
        for (int j = 0; j < m; j++) {
            int   s  = __shfl_sync(0xffffffffu, idx, j);
            float wj = __shfl_sync(0xffffffffu, wt, j);
            acc += g_h2[(size_t)s * 32 + lane] * wj;
        }
    }
    acc = acc * dv + b2[lane];
    float mx = acc;
    #pragma unroll
    for (int o = 16; o > 0; o >>= 1) mx = fmaxf(mx, __shfl_xor_sync(0xffffffffu, mx, o));
    float ex = expf(acc - mx);
    float s = ex;
    #pragma unroll
    for (int o = 16; o > 0; o >>= 1) s += __shfl_xor_sync(0xffffffffu, s, o);
    out[(size_t)v * 32 + lane] = acc - mx - logf(s);
}

// ---------------- launcher: fork graph-prep onto a side stream ----------------
extern "C" void kernel_launch(void* const* d_in, const int* in_sizes, int n_in,
                              void* d_out, int out_size) {
    const float* x  = (const float*)d_in[0];
    const float* W1 = (const float*)d_in[1];
    const float* b1 = (const float*)d_in[2];
    const float* W2 = (const float*)d_in[3];
    const float* b2 = (const float*)d_in[4];
    const int*   ei = (const int*)d_in[5];
    float* out = (float*)d_out;

    static cudaStream_t s_prep = nullptr;
    static cudaEvent_t  ev_fork = nullptr, ev_join = nullptr;
    if (s_prep == nullptr) {
        cudaStreamCreateWithFlags(&s_prep, cudaStreamNonBlocking);
        cudaEventCreateWithFlags(&ev_fork, cudaEventDisableTiming);
        cudaEventCreateWithFlags(&ev_join, cudaEventDisableTiming);
    }

    // fork: graph prep on side stream, GEMM1 on main stream (independent)
    cudaEventRecord(ev_fork, 0);
    cudaStreamWaitEvent(s_prep, ev_fork, 0);

    k_zero   <<<(NN + 255) / 256, 256, 0, s_prep>>>();
    k_hist   <<<(EE / 4 + 255) / 256, 256, 0, s_prep>>>(ei);
    k_bsum   <<<NB, SCAN_B, 0, s_prep>>>();
    k_bscan  <<<1, 32, 0, s_prep>>>();
    k_off    <<<NB, SCAN_B, 0, s_prep>>>();
    k_scatter<<<(EE / 4 + 255) / 256, 256, 0, s_prep>>>(ei);
    cudaEventRecord(ev_join, s_prep);

    k_gemm1  <<<(NN + 63) / 64, 256>>>(x, W1);

    // join: agg1 needs both h1 (main) and CSR/dinv (prep)
    cudaStreamWaitEvent(0, ev_join, 0);

    k_agg1   <<<(NN * 32 + 255) / 256, 256>>>(b1);
    k_gemm2  <<<(NN + 127) / 128, 256>>>(W2);
    k_agg2   <<<(NN * 32 + 255) / 256, 256>>>(b2, out);
}

// round 6
// speedup vs baseline: 1.4898x; 1.0253x over previous
#include <cuda_runtime.h>
#include <stdint.h>

#define NN   50000
#define EE   800000
#define DD   128
#define CC   32
#define SCAN_B 1024
#define NB   ((NN + SCAN_B - 1) / SCAN_B)   // 49 scan blocks

// ---------------- scratch (static device globals; no runtime alloc) ----------------
__device__ int   g_cnt[NN];
__device__ int   g_cursor[NN];
__device__ int   g_off[NN + 1];
__device__ float g_dinv[NN];
__device__ int   g_csr[EE];
__device__ int   g_bsum[NB];
__device__ float g_h1[NN * DD];   // x @ W1
__device__ float g_a1[NN * DD];   // aggregated + relu + dropout
__device__ float g_h2[NN * CC];   // a1 @ W2

// ---------------- graph prep ----------------
__global__ void k_zero() {
    int i = blockIdx.x * blockDim.x + threadIdx.x;
    if (i < NN) g_cnt[i] = 0;
}

// 8 edges per thread, 2x int4 loads -> 8 outstanding atomics per thread
__global__ void k_hist(const int* __restrict__ ei) {
    int t = blockIdx.x * blockDim.x + threadIdx.x;
    int e = t * 8;
    if (e < EE) {
        int4 d0 = *(const int4*)(ei + EE + e);
        int4 d1 = *(const int4*)(ei + EE + e + 4);
        atomicAdd(&g_cnt[d0.x], 1);
        atomicAdd(&g_cnt[d0.y], 1);
        atomicAdd(&g_cnt[d0.z], 1);
        atomicAdd(&g_cnt[d0.w], 1);
        atomicAdd(&g_cnt[d1.x], 1);
        atomicAdd(&g_cnt[d1.y], 1);
        atomicAdd(&g_cnt[d1.z], 1);
        atomicAdd(&g_cnt[d1.w], 1);
    }
}

// ---- 2-kernel scan: block sums -> offsets (scan-of-sums folded into k_off) ----
__global__ void k_bsum() {
    __shared__ int wsum[32];
    int idx = blockIdx.x * SCAN_B + threadIdx.x;
    int lane = threadIdx.x & 31, wid = threadIdx.x >> 5;
    int v = (idx < NN) ? g_cnt[idx] : 0;
    if (idx < NN) g_dinv[idx] = rsqrtf((float)(v + 1));
    int x = v;
    #pragma unroll
    for (int o = 16; o > 0; o >>= 1) x += __shfl_down_sync(0xffffffffu, x, o);
    if (lane == 0) wsum[wid] = x;
    __syncthreads();
    if (wid == 0) {
        int y = (lane < SCAN_B / 32) ? wsum[lane] : 0;
        #pragma unroll
        for (int o = 16; o > 0; o >>= 1) y += __shfl_down_sync(0xffffffffu, y, o);
        if (lane == 0) g_bsum[blockIdx.x] = y;
    }
}

__global__ void k_off() {
    __shared__ int wsum[32];
    __shared__ int s_bpre;    // exclusive prefix of block sums for this block
    __shared__ int s_total;
    int idx = blockIdx.x * SCAN_B + threadIdx.x;
    int lane = threadIdx.x & 31, wid = threadIdx.x >> 5;

    // warp 0: redundant scan of the 49 block sums (two strips of 32)
    if (wid == 0) {
        int carry = 0;
        for (int base = 0; base < NB; base += 32) {
            int i = base + lane;
            int v = (i < NB) ? g_bsum[i] : 0;
            int x = v;
            #pragma unroll
            for (int o = 1; o < 32; o <<= 1) {
                int t = __shfl_up_sync(0xffffffffu, x, o);
                if (lane >= o) x += t;
            }
            if (i == blockIdx.x) s_bpre = carry + x - v;
            carry += __shfl_sync(0xffffffffu, x, 31);
        }
        if (lane == 0) s_total = carry;
    }

    int v = (idx < NN) ? g_cnt[idx] : 0;
    int x = v;
    #pragma unroll
    for (int o = 1; o < 32; o <<= 1) {
        int t = __shfl_up_sync(0xffffffffu, x, o);
        if (lane >= o) x += t;
    }
    if (lane == 31) wsum[wid] = x;
    __syncthreads();
    if (wid == 0) {
        int y = (lane < SCAN_B / 32) ? wsum[lane] : 0;
        #pragma unroll
        for (int o = 1; o < 32; o <<= 1) {
            int t = __shfl_up_sync(0xffffffffu, y, o);
            if (lane >= o) y += t;
        }
        wsum[lane] = y;
    }
    __syncthreads();
    if (idx < NN) {
        int off = s_bpre + (wid > 0 ? wsum[wid - 1] : 0) + x - v;
        g_off[idx] = off;
        g_cursor[idx] = off;
    }
    if (blockIdx.x == 0 && threadIdx.x == 0) g_off[NN] = s_total;
}

// 8 edges per thread, cursor pre-seeded with offsets
__global__ void k_scatter(const int* __restrict__ ei) {
    int t = blockIdx.x * blockDim.x + threadIdx.x;
    int e = t * 8;
    if (e < EE) {
        int4 s0 = *(const int4*)(ei + e);
        int4 s1 = *(const int4*)(ei + e + 4);
        int4 d0 = *(const int4*)(ei + EE + e);
        int4 d1 = *(const int4*)(ei + EE + e + 4);
        g_csr[atomicAdd(&g_cursor[d0.x], 1)] = s0.x;
        g_csr[atomicAdd(&g_cursor[d0.y], 1)] = s0.y;
        g_csr[atomicAdd(&g_cursor[d0.z], 1)] = s0.z;
        g_csr[atomicAdd(&g_cursor[d0.w], 1)] = s0.w;
        g_csr[atomicAdd(&g_cursor[d1.x], 1)] = s1.x;
        g_csr[atomicAdd(&g_cursor[d1.y], 1)] = s1.y;
        g_csr[atomicAdd(&g_cursor[d1.z], 1)] = s1.z;
        g_csr[atomicAdd(&g_cursor[d1.w], 1)] = s1.w;
    }
}

// ---------------- GEMM1: h1[50000,128] = X[50000,128] @ W1[128,128] ----------------
__global__ void k_gemm1(const float* __restrict__ X, const float* __restrict__ W) {
    __shared__ float As[32][72];
    __shared__ float Bs[32][128];
    int m0 = blockIdx.x * 64;
    int tid = threadIdx.x;
    int tx = tid & 31;
    int ty = tid >> 5;
    float acc[8][4];
    #pragma unroll
    for (int i = 0; i < 8; i++)
        #pragma unroll
        for (int j = 0; j < 4; j++) acc[i][j] = 0.f;

    for (int kc = 0; kc < 128; kc += 32) {
        #pragma unroll
        for (int t = tid; t < 512; t += 256) {
            int m = t >> 3, q = t & 7;
            int gm = m0 + m;
            float4 v = make_float4(0.f, 0.f, 0.f, 0.f);
            if (gm < NN) v = *(const float4*)(X + (size_t)gm * 128 + kc + q * 4);
            As[q * 4 + 0][m] = v.x;
            As[q * 4 + 1][m] = v.y;
            As[q * 4 + 2][m] = v.z;
            As[q * 4 + 3][m] = v.w;
        }
        #pragma unroll
        for (int t = tid; t < 1024; t += 256) {
            int k = t >> 5, q = t & 31;
            *(float4*)&Bs[k][q * 4] = *(const float4*)(W + (size_t)(kc + k) * 128 + q * 4);
        }
        __syncthreads();
        #pragma unroll
        for (int k = 0; k < 32; k++) {
            float4 a0 = *(const float4*)&As[k][ty * 8];
            float4 a1 = *(const float4*)&As[k][ty * 8 + 4];
            float4 b  = *(const float4*)&Bs[k][tx * 4];
            float av[8] = {a0.x, a0.y, a0.z, a0.w, a1.x, a1.y, a1.z, a1.w};
            float bv[4] = {b.x, b.y, b.z, b.w};
            #pragma unroll
            for (int i = 0; i < 8; i++)
                #pragma unroll
                for (int j = 0; j < 4; j++) acc[i][j] += av[i] * bv[j];
        }
        __syncthreads();
    }
    #pragma unroll
    for (int i = 0; i < 8; i++) {
        int gm = m0 + ty * 8 + i;
        if (gm < NN) {
            float4 o = make_float4(acc[i][0], acc[i][1], acc[i][2], acc[i][3]);
            *(float4*)(g_h1 + (size_t)gm * 128 + tx * 4) = o;
        }
    }
}

// ---------------- threefry (JAX partitionable, key (0,42)) ----------------
__device__ __forceinline__ uint32_t tf_bits(uint32_t c1) {
    const uint32_t ks0 = 0u;
    const uint32_t ks1 = 42u;
    const uint32_t ks2 = 0x1BD11BDAu ^ 0u ^ 42u;
    uint32_t x0 = 0u + ks0;
    uint32_t x1 = c1 + ks1;
#define TF_R(r) { x0 += x1; x1 = __funnelshift_l(x1, x1, (r)); x1 ^= x0; }
    TF_R(13) TF_R(15) TF_R(26) TF_R(6)
    x0 += ks1; x1 += ks2 + 1u;
    TF_R(17) TF_R(29) TF_R(16) TF_R(24)
    x0 += ks2; x1 += ks0 + 2u;
    TF_R(13) TF_R(15) TF_R(26) TF_R(6)
    x0 += ks0; x1 += ks1 + 3u;
    TF_R(17) TF_R(29) TF_R(16) TF_R(24)
    x0 += ks1; x1 += ks2 + 4u;
    TF_R(13) TF_R(15) TF_R(26) TF_R(6)
    x0 += ks2; x1 += ks0 + 5u;
#undef TF_R
    return x0 ^ x1;
}

// ---------------- aggregate layer 1 + bias + relu + dropout (fused) -----------
// warp per node, lane handles features [4*lane, 4*lane+4); neighbor loop unrolled x4
__global__ void k_agg1(const float* __restrict__ b1) {
    int w = (blockIdx.x * blockDim.x + threadIdx.x) >> 5;
    int lane = threadIdx.x & 31;
    if (w >= NN) return;
    int v = w;
    int beg = g_off[v], end = g_off[v + 1];
    float dv = g_dinv[v];

    float4 a = *(const float4*)(g_h1 + (size_t)v * 128 + lane * 4);
    float4 acc = make_float4(a.x * dv, a.y * dv, a.z * dv, a.w * dv);

    for (int base = beg; base < end; base += 32) {
        int n = end - base;
        int idx = 0; float wt = 0.f;
        if (lane < n) { idx = g_csr[base + lane]; wt = g_dinv[idx]; }
        int m = n < 32 ? n : 32;
        int j = 0;
        for (; j + 4 <= m; j += 4) {
            int   s0 = __shfl_sync(0xffffffffu, idx, j);
            int   s1 = __shfl_sync(0xffffffffu, idx, j + 1);
            int   s2 = __shfl_sync(0xffffffffu, idx, j + 2);
            int   s3 = __shfl_sync(0xffffffffu, idx, j + 3);
            float w0 = __shfl_sync(0xffffffffu, wt, j);
            float w1 = __shfl_sync(0xffffffffu, wt, j + 1);
            float w2 = __shfl_sync(0xffffffffu, wt, j + 2);
            float w3 = __shfl_sync(0xffffffffu, wt, j + 3);
            float4 h0 = *(const float4*)(g_h1 + (size_t)s0 * 128 + lane * 4);
            float4 h1 = *(const float4*)(g_h1 + (size_t)s1 * 128 + lane * 4);
            float4 h2 = *(const float4*)(g_h1 + (size_t)s2 * 128 + lane * 4);
            float4 h3 = *(const float4*)(g_h1 + (size_t)s3 * 128 + lane * 4);
            acc.x += h0.x * w0; acc.y += h0.y * w0; acc.z += h0.z * w0; acc.w += h0.w * w0;
            acc.x += h1.x * w1; acc.y += h1.y * w1; acc.z += h1.z * w1; acc.w += h1.w * w1;
            acc.x += h2.x * w2; acc.y += h2.y * w2; acc.z += h2.z * w2; acc.w += h2.w * w2;
            acc.x += h3.x * w3; acc.y += h3.y * w3; acc.z += h3.z * w3; acc.w += h3.w * w3;
        }
        for (; j < m; j++) {
            int   s  = __shfl_sync(0xffffffffu, idx, j);
            float wj = __shfl_sync(0xffffffffu, wt, j);
            float4 hv = *(const float4*)(g_h1 + (size_t)s * 128 + lane * 4);
            acc.x += hv.x * wj;
            acc.y += hv.y * wj;
            acc.z += hv.z * wj;
            acc.w += hv.w * wj;
        }
    }
    float4 bb = *(const float4*)(b1 + lane * 4);
    float r[4];
    r[0] = fmaxf(acc.x * dv + bb.x, 0.f);
    r[1] = fmaxf(acc.y * dv + bb.y, 0.f);
    r[2] = fmaxf(acc.z * dv + bb.z, 0.f);
    r[3] = fmaxf(acc.w * dv + bb.w, 0.f);

    uint32_t i0 = (uint32_t)v * 128u + (uint32_t)lane * 4u;
    #pragma unroll
    for (int q = 0; q < 4; q++) {
        uint32_t bits = tf_bits(i0 + q);
        r[q] = (bits & 0x80000000u) ? 0.f : r[q] * 2.f;
    }
    *(float4*)(g_a1 + (size_t)v * 128 + lane * 4) = make_float4(r[0], r[1], r[2], r[3]);
}

// ---------------- GEMM2: h2[50000,32] = a1[50000,128] @ W2[128,32] ----------------
__global__ void k_gemm2(const float* __restrict__ W) {
    __shared__ float As[32][132];
    __shared__ float Bs[32][32];
    int m0 = blockIdx.x * 128;
    int tid = threadIdx.x;
    int tx = tid & 7;
    int ty = tid >> 3;
    float acc[4][4];
    #pragma unroll
    for (int i = 0; i < 4; i++)
        #pragma unroll
        for (int j = 0; j < 4; j++) acc[i][j] = 0.f;

    for (int kc = 0; kc < 128; kc += 32) {
        #pragma unroll
        for (int t = tid; t < 1024; t += 256) {
            int m = t >> 3, q = t & 7;
            int gm = m0 + m;
            float4 v = make_float4(0.f, 0.f, 0.f, 0.f);
            if (gm < NN) v = *(const float4*)(g_a1 + (size_t)gm * 128 + kc + q * 4);
            As[q * 4 + 0][m] = v.x;
            As[q * 4 + 1][m] = v.y;
            As[q * 4 + 2][m] = v.z;
            As[q * 4 + 3][m] = v.w;
        }
        if (tid < 256) {
            int k = tid >> 3, q = tid & 7;
            *(float4*)&Bs[k][q * 4] = *(const float4*)(W + (size_t)(kc + k) * 32 + q * 4);
        }
        __syncthreads();
        #pragma unroll
        for (int k = 0; k < 32; k++) {
            float4 a = *(const float4*)&As[k][ty * 4];
            float4 b = *(const float4*)&Bs[k][tx * 4];
            float av[4] = {a.x, a.y, a.z, a.w};
            float bv[4] = {b.x, b.y, b.z, b.w};
            #pragma unroll
            for (int i = 0; i < 4; i++)
                #pragma unroll
                for (int j = 0; j < 4; j++) acc[i][j] += av[i] * bv[j];
        }
        __syncthreads();
    }
    #pragma unroll
    for (int i = 0; i < 4; i++) {
        int gm = m0 + ty * 4 + i;
        if (gm < NN) {
            float4 o = make_float4(acc[i][0], acc[i][1], acc[i][2], acc[i][3]);
            *(float4*)(g_h2 + (size_t)gm * 32 + tx * 4) = o;
        }
    }
}

// ---------------- aggregate layer 2 + bias + log_softmax ----------------
__global__ void k_agg2(const float* __restrict__ b2, float* __restrict__ out) {
    int w = (blockIdx.x * blockDim.x + threadIdx.x) >> 5;
    int lane = threadIdx.x & 31;
    if (w >= NN) return;
    int v = w;
    int beg = g_off[v], end = g_off[v + 1];
    float dv = g_dinv[v];
    float acc = g_h2[(size_t)v * 32 + lane] * dv;

    for (int base = beg; base < end; base += 32) {
        int n = end - base;
        int idx = 0; float wt = 0.f;
        if (lane < n) { idx = g_csr[base + lane]; wt = g_dinv[idx]; }
        int m = n < 32 ? n : 32;
        int j = 0;
        for (; j + 4 <= m; j += 4) {
            int   s0 = __shfl_sync(0xffffffffu, idx, j);
            int   s1 = __shfl_sync(0xffffffffu, idx, j + 1);
            int   s2 = __shfl_sync(0xffffffffu, idx, j + 2);
            int   s3 = __shfl_sync(0xffffffffu, idx, j + 3);
            float w0 = __shfl_sync(0xffffffffu, wt, j);
            float w1 = __shfl_sync(0xffffffffu, wt, j + 1);
            float w2 = __shfl_sync(0xffffffffu, wt, j + 2);
            float w3 = __shfl_sync(0xffffffffu, wt, j + 3);
            float h0 = g_h2[(size_t)s0 * 32 + lane];
            float h1 = g_h2[(size_t)s1 * 32 + lane];
            float h2 = g_h2[(size_t)s2 * 32 + lane];
            float h3 = g_h2[(size_t)s3 * 32 + lane];
            acc += h0 * w0;
            acc += h1 * w1;
            acc += h2 * w2;
            acc += h3 * w3;
        }
        for (; j < m; j++) {
            int   s  = __shfl_sync(0xffffffffu, idx, j);
            float wj = __shfl_sync(0xffffffffu, wt, j);
            acc += g_h2[(size_t)s * 32 + lane] * wj;
        }
    }
    acc = acc * dv + b2[lane];
    float mx = acc;
    #pragma unroll
    for (int o = 16; o > 0; o >>= 1) mx = fmaxf(mx, __shfl_xor_sync(0xffffffffu, mx, o));
    float ex = __expf(acc - mx);
    float s = ex;
    #pragma unroll
    for (int o = 16; o > 0; o >>= 1) s += __shfl_xor_sync(0xffffffffu, s, o);
    out[(size_t)v * 32 + lane] = acc - mx - __logf(s);
}

// ---------------- launcher: fork graph-prep onto a side stream ----------------
extern "C" void kernel_launch(void* const* d_in, const int* in_sizes, int n_in,
                              void* d_out, int out_size) {
    const float* x  = (const float*)d_in[0];
    const float* W1 = (const float*)d_in[1];
    const float* b1 = (const float*)d_in[2];
    const float* W2 = (const float*)d_in[3];
    const float* b2 = (const float*)d_in[4];
    const int*   ei = (const int*)d_in[5];
    float* out = (float*)d_out;

    static cudaStream_t s_prep = nullptr;
    static cudaEvent_t  ev_fork = nullptr, ev_join = nullptr;
    if (s_prep == nullptr) {
        cudaStreamCreateWithFlags(&s_prep, cudaStreamNonBlocking);
        cudaEventCreateWithFlags(&ev_fork, cudaEventDisableTiming);
        cudaEventCreateWithFlags(&ev_join, cudaEventDisableTiming);
    }

    // fork: graph prep on side stream, GEMM1 on main stream (independent)
    cudaEventRecord(ev_fork, 0);
    cudaStreamWaitEvent(s_prep, ev_fork, 0);

    k_zero   <<<(NN + 255) / 256, 256, 0, s_prep>>>();
    k_hist   <<<(EE / 8 + 255) / 256, 256, 0, s_prep>>>(ei);
    k_bsum   <<<NB, SCAN_B, 0, s_prep>>>();
    k_off    <<<NB, SCAN_B, 0, s_prep>>>();
    k_scatter<<<(EE / 8 + 255) / 256, 256, 0, s_prep>>>(ei);
    cudaEventRecord(ev_join, s_prep);

    k_gemm1  <<<(NN + 63) / 64, 256>>>(x, W1);

    // join: agg1 needs both h1 (main) and CSR/dinv (prep)
    cudaStreamWaitEvent(0, ev_join, 0);

    k_agg1   <<<(NN * 32 + 255) / 256, 256>>>(b1);
    k_gemm2  <<<(NN + 127) / 128, 256>>>(W2);
    k_agg2   <<<(NN * 32 + 255) / 256, 256>>>(b2, out);
}